// round 2
// baseline (speedup 1.0000x reference)
#include <cuda_runtime.h>
#include <cstdint>

#define B_ 64
#define S_ 2048
#define H_ 512

// ---- scratch (device globals: no allocation allowed) ----
__device__ float g_c[B_ * H_];                 // e_fin[b,k] + attn_b[k]
__device__ float g_scores_part[4 * B_ * S_];   // per-k-tile partial scores
__device__ float g_weights[B_ * S_];           // softmax weights
__device__ float g_ctx_part[16 * B_ * H_];     // per-s-chunk partial context

__device__ __forceinline__ float fast_tanh(float x) {
    x = fminf(fmaxf(x, -15.f), 15.f);
    float e = __expf(2.f * x);
    return __fdividef(e - 1.f, e + 1.f);   // abs err ~1e-6, no overflow after clamp
}

// ---- K1: c[b,k] = sum_h fin[b,h] * attn_w[k, H+h] + attn_b[k] ----
__global__ void cfin_kernel(const float* __restrict__ fin,
                            const float* __restrict__ attn_w,
                            const float* __restrict__ attn_b) {
    __shared__ float fs[H_];
    const int b = blockIdx.x;
    const int k = threadIdx.x;   // 512 threads
    fs[k] = fin[b * H_ + k];
    __syncthreads();
    const float* w = attn_w + (size_t)k * (2 * H_) + H_;
    float s = attn_b[k];
#pragma unroll 8
    for (int h = 0; h < H_; h++) s = fmaf(fs[h], w[h], s);
    g_c[b * H_ + k] = s;
}

// ---- K2: fused GEMM(131072x512x512) + tanh + v-dot -> partial scores ----
// Block: 128 s-rows x 128 k-cols, 256 threads, 8x8 microtile, f32x2 packed FMA.
__global__ __launch_bounds__(256, 2)
void scores_kernel(const float* __restrict__ enc,
                   const float* __restrict__ attn_w,
                   const float* __restrict__ v_w) {
    __shared__ __align__(16) float As[16][132];   // [h][s], row = 528B (16B mult)
    __shared__ __align__(16) float Bs[16][132];   // [h][k]
    __shared__ float red[128][17];

    const int kt = blockIdx.x;   // 0..3   (k tile)
    const int st = blockIdx.y;   // 0..15  (s tile)
    const int b  = blockIdx.z;   // 0..63
    const int tid = threadIdx.x;
    const int tx = tid & 15;
    const int ty = tid >> 4;

    const float* Ab = enc + ((size_t)b * S_ + st * 128) * H_;
    const float* Bb = attn_w + (size_t)(kt * 128) * (2 * H_);

    unsigned long long acc2[8][4];   // 8 s-rows x 4 f32x2 pairs (8 k-cols)
#pragma unroll
    for (int i = 0; i < 8; i++)
#pragma unroll
        for (int j = 0; j < 4; j++) acc2[i][j] = 0ULL;

    for (int h0 = 0; h0 < H_; h0 += 16) {
        // load 128x16 tiles of A (enc) and B (w_enc), transposed into [h][row]
#pragma unroll
        for (int q = 0; q < 2; q++) {
            int f  = tid + 256 * q;
            int r  = f >> 2;           // row 0..127
            int c4 = (f & 3) << 2;     // h offset 0,4,8,12
            float4 av = *(const float4*)(Ab + (size_t)r * H_ + h0 + c4);
            As[c4 + 0][r] = av.x; As[c4 + 1][r] = av.y;
            As[c4 + 2][r] = av.z; As[c4 + 3][r] = av.w;
            float4 bv = *(const float4*)(Bb + (size_t)r * (2 * H_) + h0 + c4);
            Bs[c4 + 0][r] = bv.x; Bs[c4 + 1][r] = bv.y;
            Bs[c4 + 2][r] = bv.z; Bs[c4 + 3][r] = bv.w;
        }
        __syncthreads();
#pragma unroll
        for (int hh = 0; hh < 16; hh++) {
            float a[8];
            *(float4*)&a[0] = *(const float4*)&As[hh][ty * 8];
            *(float4*)&a[4] = *(const float4*)&As[hh][ty * 8 + 4];
            unsigned long long b2[4];
            *(ulonglong2*)&b2[0] = *(const ulonglong2*)&Bs[hh][tx * 8];
            *(ulonglong2*)&b2[2] = *(const ulonglong2*)&Bs[hh][tx * 8 + 4];
            unsigned long long a2[8];
#pragma unroll
            for (int i = 0; i < 8; i++)
                asm("mov.b64 %0, {%1, %1};" : "=l"(a2[i]) : "f"(a[i]));
#pragma unroll
            for (int i = 0; i < 8; i++)
#pragma unroll
                for (int j = 0; j < 4; j++)
                    asm("fma.rn.f32x2 %0, %1, %2, %0;"
                        : "+l"(acc2[i][j]) : "l"(a2[i]), "l"(b2[j]));
        }
        __syncthreads();
    }

    // epilogue: tanh(e + c) * v, reduce over this block's 128 k
    const int kg = kt * 128 + tx * 8;
    float cv[8], vv[8];
#pragma unroll
    for (int j = 0; j < 8; j++) {
        cv[j] = g_c[b * H_ + kg + j];
        vv[j] = v_w[kg + j];
    }
#pragma unroll
    for (int i = 0; i < 8; i++) {
        float s = 0.f;
#pragma unroll
        for (int j = 0; j < 4; j++) {
            float lo, hi;
            asm("mov.b64 {%0, %1}, %2;" : "=f"(lo), "=f"(hi) : "l"(acc2[i][j]));
            s += fast_tanh(lo + cv[2 * j])     * vv[2 * j];
            s += fast_tanh(hi + cv[2 * j + 1]) * vv[2 * j + 1];
        }
        red[ty * 8 + i][tx] = s;
    }
    __syncthreads();
    if (tid < 128) {
        float s = 0.f;
#pragma unroll
        for (int t = 0; t < 16; t++) s += red[tid][t];
        g_scores_part[((size_t)kt * B_ + b) * S_ + st * 128 + tid] = s;
    }
}

// ---- K3: softmax over S per batch ----
__global__ void softmax_kernel() {
    const int b = blockIdx.x;
    const int tid = threadIdx.x;   // 256
    __shared__ float sbuf[256];

    float m = -1e30f;
    for (int i = tid; i < S_; i += 256) {
        float v = g_scores_part[0 * B_ * S_ + b * S_ + i]
                + g_scores_part[1 * B_ * S_ + b * S_ + i]
                + g_scores_part[2 * B_ * S_ + b * S_ + i]
                + g_scores_part[3 * B_ * S_ + b * S_ + i];
        g_weights[b * S_ + i] = v;
        m = fmaxf(m, v);
    }
    sbuf[tid] = m; __syncthreads();
    for (int o = 128; o > 0; o >>= 1) {
        if (tid < o) sbuf[tid] = fmaxf(sbuf[tid], sbuf[tid + o]);
        __syncthreads();
    }
    m = sbuf[0]; __syncthreads();

    float sum = 0.f;
    for (int i = tid; i < S_; i += 256) {
        float e = __expf(g_weights[b * S_ + i] - m);
        g_weights[b * S_ + i] = e;
        sum += e;
    }
    sbuf[tid] = sum; __syncthreads();
    for (int o = 128; o > 0; o >>= 1) {
        if (tid < o) sbuf[tid] += sbuf[tid + o];
        __syncthreads();
    }
    float inv = __fdividef(1.f, sbuf[0]);
    for (int i = tid; i < S_; i += 256) g_weights[b * S_ + i] *= inv;
}

// ---- K4: partial context per 128-s chunk ----
__global__ void context_kernel(const float* __restrict__ enc) {
    const int sc = blockIdx.x;   // 0..15
    const int b  = blockIdx.y;
    const int tid = threadIdx.x; // 512 (= one h each)
    __shared__ float ws[128];
    if (tid < 128) ws[tid] = g_weights[b * S_ + sc * 128 + tid];
    __syncthreads();
    const float* e = enc + ((size_t)b * S_ + sc * 128) * H_ + tid;
    float acc = 0.f;
#pragma unroll 8
    for (int s = 0; s < 128; s++) acc = fmaf(ws[s], e[(size_t)s * H_], acc);
    g_ctx_part[((size_t)sc * B_ + b) * H_ + tid] = acc;
}

// ---- K5: reduce the 16 partial contexts ----
__global__ void reduce_ctx(float* __restrict__ out) {
    int i = blockIdx.x * 256 + threadIdx.x;   // 32768 outputs
    float s = 0.f;
#pragma unroll
    for (int ch = 0; ch < 16; ch++) s += g_ctx_part[(size_t)ch * B_ * H_ + i];
    out[i] = s;
}

extern "C" void kernel_launch(void* const* d_in, const int* in_sizes, int n_in,
                              void* d_out, int out_size) {
    const float* enc    = (const float*)d_in[0];
    const float* fin    = (const float*)d_in[1];
    const float* attn_w = (const float*)d_in[2];
    const float* attn_b = (const float*)d_in[3];
    const float* v_w    = (const float*)d_in[4];
    float* out = (float*)d_out;

    cfin_kernel<<<B_, H_>>>(fin, attn_w, attn_b);
    scores_kernel<<<dim3(4, 16, B_), 256>>>(enc, attn_w, v_w);
    softmax_kernel<<<B_, 256>>>();
    context_kernel<<<dim3(16, B_), 512>>>(enc);
    reduce_ctx<<<(B_ * H_) / 256, 256>>>(out);
}

// round 4
// speedup vs baseline: 1.6242x; 1.6242x over previous
#include <cuda_runtime.h>
#include <cuda_bf16.h>
#include <mma.h>
#include <cstdint>

using namespace nvcuda;

#define B_ 64
#define S_ 2048
#define H_ 512

// ---------------- scratch (device globals; no allocation allowed) ----------
__device__ float g_c[B_ * H_];                       // e_fin[b,k] + attn_b[k]
__device__ float g_scores_part[4 * B_ * S_];         // per-k-tile partial scores
__device__ float g_weights[B_ * S_];                 // softmax weights
__device__ float g_ctx_part[16 * B_ * H_];           // per-s-chunk partial context
__device__ __nv_bfloat16 g_enc_hi[(size_t)B_ * S_ * H_];   // 128 MB
__device__ __nv_bfloat16 g_enc_lo[(size_t)B_ * S_ * H_];   // 128 MB
__device__ __nv_bfloat16 g_w_hi[H_ * H_];
__device__ __nv_bfloat16 g_w_lo[H_ * H_];

// ---------------- helpers ---------------------------------------------------
__device__ __forceinline__ uint32_t smem_u32(const void* p) {
    uint32_t a;
    asm("{ .reg .u64 t; cvta.to.shared.u64 t, %1; cvt.u32.u64 %0, t; }" : "=r"(a) : "l"(p));
    return a;
}
__device__ __forceinline__ void cp16(uint32_t dst, const void* src) {
    asm volatile("cp.async.cg.shared.global [%0], [%1], 16;" :: "r"(dst), "l"(src) : "memory");
}
#define CP_COMMIT() asm volatile("cp.async.commit_group;" ::: "memory")

__device__ __forceinline__ float fast_tanh(float x) {
    x = fminf(fmaxf(x, -15.f), 15.f);
    float e = __expf(2.f * x);
    return __fdividef(e - 1.f, e + 1.f);
}

// ---------------- K0a: enc f32 -> bf16 hi/lo split --------------------------
__global__ void convert_enc_kernel(const float* __restrict__ enc) {
    size_t i = (size_t)blockIdx.x * 256 + threadIdx.x;   // one float4 per thread
    float4 x = ((const float4*)enc)[i];
    float v[4] = {x.x, x.y, x.z, x.w};
    ushort4 ho, lo;
    unsigned short* hp = &ho.x;
    unsigned short* lp = &lo.x;
#pragma unroll
    for (int j = 0; j < 4; j++) {
        __nv_bfloat16 h = __float2bfloat16(v[j]);
        __nv_bfloat16 l = __float2bfloat16(v[j] - __bfloat162float(h));
        hp[j] = __bfloat16_as_ushort(h);
        lp[j] = __bfloat16_as_ushort(l);
    }
    ((ushort4*)g_enc_hi)[i] = ho;
    ((ushort4*)g_enc_lo)[i] = lo;
}

// ---------------- K0b: w_enc f32 -> bf16 hi/lo ------------------------------
__global__ void convert_w_kernel(const float* __restrict__ attn_w) {
    int idx = blockIdx.x * 256 + threadIdx.x;            // 262144
    int k = idx >> 9, h = idx & 511;
    float x = attn_w[(size_t)k * (2 * H_) + h];          // w_enc = attn_w[:, :H]
    __nv_bfloat16 hi = __float2bfloat16(x);
    g_w_hi[idx] = hi;
    g_w_lo[idx] = __float2bfloat16(x - __bfloat162float(hi));
}

// ---------------- K1: c[b,k] = fin[b]·attn_w[k, H:] + b[k] ------------------
__global__ void cfin_kernel(const float* __restrict__ fin,
                            const float* __restrict__ attn_w,
                            const float* __restrict__ attn_b) {
    __shared__ float fs[H_];
    const int b = blockIdx.x;
    const int k = threadIdx.x;
    fs[k] = fin[b * H_ + k];
    __syncthreads();
    const float* w = attn_w + (size_t)k * (2 * H_) + H_;
    float s = attn_b[k];
#pragma unroll 8
    for (int h = 0; h < H_; h++) s = fmaf(fs[h], w[h], s);
    g_c[b * H_ + k] = s;
}

// ---------------- K2: wmma bf16x3 GEMM + tanh/v epilogue --------------------
// CTA tile 128(s) x 128(k), K=512 in 16 chunks of KC=32, double-buffered.
// 8 warps in 4(M) x 2(N); warp tile 32x64 = 2x4 wmma 16x16x16 accumulators.
static constexpr int KC = 32;
static constexpr int LDT = KC + 8;                 // padded smem stride (elems)
static constexpr int TILE_E = 128 * LDT;           // 5120 elems
static constexpr int TILE_B2 = TILE_E * 2;         // 10240 bytes (bf16)
static constexpr int STAGE_B = 4 * TILE_B2;        // 40960 bytes (Ah,Al,Bh,Bl)
static constexpr int CV_OFF = 2 * STAGE_B;         // 81920
static constexpr int SMEM_NEED = CV_OFF + 1024;    // + c[128], v[128]

__device__ __forceinline__ void fill_chunk(uint32_t sbase, int stage, int c,
                                           int mt, int kt, int tid) {
    // A rows: s (128), cols: h chunk (32 bf16 = 64B). B rows: k_out (128).
    const int r  = tid >> 1;            // row 0..127
    const int hb = (tid & 1) * 32;      // byte half of the 64B row
    const uint32_t tb = sbase + stage * STAGE_B;
    const uint32_t soff = (uint32_t)r * (LDT * 2) + hb;
    const char* aH = (const char*)g_enc_hi + (((size_t)mt * 128 + r) * H_ + c * KC) * 2 + hb;
    const char* aL = (const char*)g_enc_lo + (((size_t)mt * 128 + r) * H_ + c * KC) * 2 + hb;
    const char* bH = (const char*)g_w_hi   + (((size_t)kt * 128 + r) * H_ + c * KC) * 2 + hb;
    const char* bL = (const char*)g_w_lo   + (((size_t)kt * 128 + r) * H_ + c * KC) * 2 + hb;
    cp16(tb + 0 * TILE_B2 + soff,      aH);
    cp16(tb + 0 * TILE_B2 + soff + 16, aH + 16);
    cp16(tb + 1 * TILE_B2 + soff,      aL);
    cp16(tb + 1 * TILE_B2 + soff + 16, aL + 16);
    cp16(tb + 2 * TILE_B2 + soff,      bH);
    cp16(tb + 2 * TILE_B2 + soff + 16, bH + 16);
    cp16(tb + 3 * TILE_B2 + soff,      bL);
    cp16(tb + 3 * TILE_B2 + soff + 16, bL + 16);
}

__global__ __launch_bounds__(256)
void scores_wmma_kernel(const float* __restrict__ v_w) {
    extern __shared__ char smem[];
    const uint32_t sbase = smem_u32(smem);
    const int tid = threadIdx.x;
    const int wid = tid >> 5;
    const int kt = blockIdx.x;        // 0..3   (k tile of 128)
    const int mt = blockIdx.y;        // 0..1023 (s tile of 128 over B*S)
    const int b  = mt >> 4;
    const int wm = wid & 3;           // warp M index (4)
    const int wn = wid >> 2;          // warp N index (2)

    float* c_s = (float*)(smem + CV_OFF);
    float* v_s = (float*)(smem + CV_OFF + 512);
    if (tid < 128) {
        c_s[tid] = g_c[b * H_ + kt * 128 + tid];
        v_s[tid] = v_w[kt * 128 + tid];
    }

    wmma::fragment<wmma::accumulator, 16, 16, 16, float> acc[2][4];
#pragma unroll
    for (int i = 0; i < 2; i++)
#pragma unroll
        for (int j = 0; j < 4; j++) wmma::fill_fragment(acc[i][j], 0.f);

    fill_chunk(sbase, 0, 0, mt, kt, tid); CP_COMMIT();
    fill_chunk(sbase, 1, 1, mt, kt, tid); CP_COMMIT();

    for (int c = 0; c < 16; c++) {
        const int st = c & 1;
        if (c < 15) asm volatile("cp.async.wait_group 1;" ::: "memory");
        else        asm volatile("cp.async.wait_group 0;" ::: "memory");
        __syncthreads();

        const __nv_bfloat16* Ah = (const __nv_bfloat16*)(smem + st * STAGE_B + 0 * TILE_B2);
        const __nv_bfloat16* Al = (const __nv_bfloat16*)(smem + st * STAGE_B + 1 * TILE_B2);
        const __nv_bfloat16* Bh = (const __nv_bfloat16*)(smem + st * STAGE_B + 2 * TILE_B2);
        const __nv_bfloat16* Bl = (const __nv_bfloat16*)(smem + st * STAGE_B + 3 * TILE_B2);

#pragma unroll
        for (int kk = 0; kk < KC; kk += 16) {
            wmma::fragment<wmma::matrix_a, 16, 16, 16, __nv_bfloat16, wmma::row_major> ah[2], al[2];
            wmma::fragment<wmma::matrix_b, 16, 16, 16, __nv_bfloat16, wmma::col_major> bh[4], bl[4];
#pragma unroll
            for (int i = 0; i < 2; i++) {
                const int row = wm * 32 + i * 16;
                wmma::load_matrix_sync(ah[i], Ah + row * LDT + kk, LDT);
                wmma::load_matrix_sync(al[i], Al + row * LDT + kk, LDT);
            }
#pragma unroll
            for (int j = 0; j < 4; j++) {
                const int col = wn * 64 + j * 16;
                wmma::load_matrix_sync(bh[j], Bh + col * LDT + kk, LDT);
                wmma::load_matrix_sync(bl[j], Bl + col * LDT + kk, LDT);
            }
#pragma unroll
            for (int i = 0; i < 2; i++)
#pragma unroll
                for (int j = 0; j < 4; j++) {
                    wmma::mma_sync(acc[i][j], ah[i], bh[j], acc[i][j]);
                    wmma::mma_sync(acc[i][j], ah[i], bl[j], acc[i][j]);
                    wmma::mma_sync(acc[i][j], al[i], bh[j], acc[i][j]);
                }
        }
        __syncthreads();   // all warps done reading before refill overwrites
        if (c + 2 < 16) { fill_chunk(sbase, st, c + 2, mt, kt, tid); CP_COMMIT(); }
    }

    // ---- epilogue: e[s][k] -> smem, then sum_k tanh(e + c) * v per row -----
    float* e_s = (float*)smem;         // 128 x 128 f32 = 64KB (tiles dead now)
    __syncthreads();
#pragma unroll
    for (int i = 0; i < 2; i++)
#pragma unroll
        for (int j = 0; j < 4; j++)
            wmma::store_matrix_sync(e_s + (wm * 32 + i * 16) * 128 + wn * 64 + j * 16,
                                    acc[i][j], 128, wmma::mem_row_major);
    __syncthreads();

    const int r  = tid >> 1;
    const int c0 = (tid & 1) * 64;
    float s = 0.f;
#pragma unroll 8
    for (int j = 0; j < 64; j++) {
        const int k = c0 + j;
        s += fast_tanh(e_s[r * 128 + k] + c_s[k]) * v_s[k];
    }
    s += __shfl_xor_sync(0xffffffffu, s, 1);
    if ((tid & 1) == 0)
        g_scores_part[(size_t)kt * (B_ * S_) + mt * 128 + r] = s;
}

// ---------------- K3: softmax over S per batch ------------------------------
__global__ void softmax_kernel() {
    const int b = blockIdx.x;
    const int tid = threadIdx.x;   // 256
    __shared__ float sbuf[256];

    float m = -1e30f;
    for (int i = tid; i < S_; i += 256) {
        float v = g_scores_part[0 * B_ * S_ + b * S_ + i]
                + g_scores_part[1 * B_ * S_ + b * S_ + i]
                + g_scores_part[2 * B_ * S_ + b * S_ + i]
                + g_scores_part[3 * B_ * S_ + b * S_ + i];
        g_weights[b * S_ + i] = v;
        m = fmaxf(m, v);
    }
    sbuf[tid] = m; __syncthreads();
    for (int o = 128; o > 0; o >>= 1) {
        if (tid < o) sbuf[tid] = fmaxf(sbuf[tid], sbuf[tid + o]);
        __syncthreads();
    }
    m = sbuf[0]; __syncthreads();

    float sum = 0.f;
    for (int i = tid; i < S_; i += 256) {
        float e = __expf(g_weights[b * S_ + i] - m);
        g_weights[b * S_ + i] = e;
        sum += e;
    }
    sbuf[tid] = sum; __syncthreads();
    for (int o = 128; o > 0; o >>= 1) {
        if (tid < o) sbuf[tid] += sbuf[tid + o];
        __syncthreads();
    }
    float inv = __fdividef(1.f, sbuf[0]);
    for (int i = tid; i < S_; i += 256) g_weights[b * S_ + i] *= inv;
}

// ---------------- K4: partial context per 128-s chunk -----------------------
__global__ void context_kernel(const float* __restrict__ enc) {
    const int sc = blockIdx.x;   // 0..15
    const int b  = blockIdx.y;
    const int tid = threadIdx.x; // 512
    __shared__ float ws[128];
    if (tid < 128) ws[tid] = g_weights[b * S_ + sc * 128 + tid];
    __syncthreads();
    const float* e = enc + ((size_t)b * S_ + sc * 128) * H_ + tid;
    float acc = 0.f;
#pragma unroll 8
    for (int s = 0; s < 128; s++) acc = fmaf(ws[s], e[(size_t)s * H_], acc);
    g_ctx_part[((size_t)sc * B_ + b) * H_ + tid] = acc;
}

// ---------------- K5: reduce partial contexts -------------------------------
__global__ void reduce_ctx(float* __restrict__ out) {
    int i = blockIdx.x * 256 + threadIdx.x;
    float s = 0.f;
#pragma unroll
    for (int ch = 0; ch < 16; ch++) s += g_ctx_part[(size_t)ch * B_ * H_ + i];
    out[i] = s;
}

extern "C" void kernel_launch(void* const* d_in, const int* in_sizes, int n_in,
                              void* d_out, int out_size) {
    const float* enc    = (const float*)d_in[0];
    const float* fin    = (const float*)d_in[1];
    const float* attn_w = (const float*)d_in[2];
    const float* attn_b = (const float*)d_in[3];
    const float* v_w    = (const float*)d_in[4];
    float* out = (float*)d_out;

    cudaFuncSetAttribute(scores_wmma_kernel,
                         cudaFuncAttributeMaxDynamicSharedMemorySize, SMEM_NEED);

    convert_enc_kernel<<<65536, 256>>>(enc);
    convert_w_kernel<<<(H_ * H_) / 256, 256>>>(attn_w);
    cfin_kernel<<<B_, H_>>>(fin, attn_w, attn_b);
    scores_wmma_kernel<<<dim3(4, 1024), 256, SMEM_NEED>>>(v_w);
    softmax_kernel<<<B_, 256>>>();
    context_kernel<<<dim3(16, B_), 512>>>(enc);
    reduce_ctx<<<(B_ * H_) / 256, 256>>>(out);
}

// round 5
// speedup vs baseline: 1.6624x; 1.0235x over previous
#include <cuda_runtime.h>
#include <cuda_bf16.h>
#include <mma.h>
#include <cstdint>

using namespace nvcuda;

#define B_ 64
#define S_ 2048
#define H_ 512

// ---------------- scratch (device globals; no allocation allowed) ----------
__device__ float g_c[B_ * H_];                       // e_fin[b,k] + attn_b[k]
__device__ float g_scores_part[2 * B_ * S_];         // per-k-half partial scores
__device__ float g_weights[B_ * S_];                 // softmax weights
__device__ float g_ctx_part[16 * B_ * H_];           // per-s-chunk partial context
__device__ __nv_bfloat16 g_enc_hi[(size_t)B_ * S_ * H_];   // 128 MB
__device__ __nv_bfloat16 g_enc_lo[(size_t)B_ * S_ * H_];   // 128 MB
__device__ __nv_bfloat16 g_w_hi[H_ * H_];
__device__ __nv_bfloat16 g_w_lo[H_ * H_];

// ---------------- helpers ---------------------------------------------------
__device__ __forceinline__ uint32_t smem_u32(const void* p) {
    uint32_t a;
    asm("{ .reg .u64 t; cvta.to.shared.u64 t, %1; cvt.u32.u64 %0, t; }" : "=r"(a) : "l"(p));
    return a;
}
__device__ __forceinline__ void cp16(uint32_t dst, const void* src) {
    asm volatile("cp.async.cg.shared.global [%0], [%1], 16;" :: "r"(dst), "l"(src) : "memory");
}
#define CP_COMMIT() asm volatile("cp.async.commit_group;" ::: "memory")

__device__ __forceinline__ float fast_tanh(float x) {
    x = fminf(fmaxf(x, -15.f), 15.f);
    float e = __expf(2.f * x);
    return __fdividef(e - 1.f, e + 1.f);
}

// ---------------- K0a: enc f32 -> bf16 hi/lo split --------------------------
__global__ void convert_enc_kernel(const float* __restrict__ enc) {
    size_t i = (size_t)blockIdx.x * 256 + threadIdx.x;   // one float4 per thread
    float4 x = ((const float4*)enc)[i];
    float v[4] = {x.x, x.y, x.z, x.w};
    ushort4 ho, lo;
    unsigned short* hp = &ho.x;
    unsigned short* lp = &lo.x;
#pragma unroll
    for (int j = 0; j < 4; j++) {
        __nv_bfloat16 h = __float2bfloat16(v[j]);
        __nv_bfloat16 l = __float2bfloat16(v[j] - __bfloat162float(h));
        hp[j] = __bfloat16_as_ushort(h);
        lp[j] = __bfloat16_as_ushort(l);
    }
    ((ushort4*)g_enc_hi)[i] = ho;
    ((ushort4*)g_enc_lo)[i] = lo;
}

// ---------------- K0b: w_enc f32 -> bf16 hi/lo ------------------------------
__global__ void convert_w_kernel(const float* __restrict__ attn_w) {
    int idx = blockIdx.x * 256 + threadIdx.x;            // 262144
    int k = idx >> 9, h = idx & 511;
    float x = attn_w[(size_t)k * (2 * H_) + h];          // w_enc = attn_w[:, :H]
    __nv_bfloat16 hi = __float2bfloat16(x);
    g_w_hi[idx] = hi;
    g_w_lo[idx] = __float2bfloat16(x - __bfloat162float(hi));
}

// ---------------- K1: c[b,k] = fin[b]·attn_w[k, H:] + b[k] ------------------
__global__ void cfin_kernel(const float* __restrict__ fin,
                            const float* __restrict__ attn_w,
                            const float* __restrict__ attn_b) {
    __shared__ float fs[H_];
    const int b = blockIdx.x;
    const int k = threadIdx.x;
    fs[k] = fin[b * H_ + k];
    __syncthreads();
    const float* w = attn_w + (size_t)k * (2 * H_) + H_;
    float s = attn_b[k];
#pragma unroll 8
    for (int h = 0; h < H_; h++) s = fmaf(fs[h], w[h], s);
    g_c[b * H_ + k] = s;
}

// ---------------- K2: wmma bf16x3 GEMM + tanh/v epilogue --------------------
// CTA tile 128(s) x 256(k); 8 warps as 2(M) x 4(N); warp tile 64x64.
// K=512 in 16 chunks of KC=32; 3-stage cp.async pipeline, one sync per chunk.
static constexpr int KC  = 32;
static constexpr int LDT = KC + 8;                    // padded stride (elems) = 80B
static constexpr int A_MAT = 128 * LDT * 2;           // 10240 B (one of hi/lo)
static constexpr int B_MAT = 256 * LDT * 2;           // 20480 B
static constexpr int OFF_AL = A_MAT;                  // 10240
static constexpr int OFF_BH = 2 * A_MAT;              // 20480
static constexpr int OFF_BL = 2 * A_MAT + B_MAT;      // 40960
static constexpr int STAGE_B = 2 * A_MAT + 2 * B_MAT; // 61440
static constexpr int NSTAGE = 3;
static constexpr int CV_OFF = NSTAGE * STAGE_B;       // 184320
static constexpr int SMEM_NEED = CV_OFF + 2048;       // + c[256], v[256]

__device__ __forceinline__ void fill_chunk(uint32_t sbase, int stage, int c,
                                           int mt, int kt, int tid) {
    const uint32_t tb = sbase + stage * STAGE_B;
    const char* eh = (const char*)g_enc_hi;
    const char* el = (const char*)g_enc_lo;
    const char* wh = (const char*)g_w_hi;
    const char* wl = (const char*)g_w_lo;
    // A: 128 rows x 64B, hi+lo = 1024 cp16
#pragma unroll
    for (int i = 0; i < 4; i++) {
        int id = i * 256 + tid;
        int r = id >> 3, sub = id & 7;
        int m = sub >> 2, p = sub & 3;
        uint32_t dst = tb + m * OFF_AL + (uint32_t)r * (LDT * 2) + p * 16;
        size_t goff = (((size_t)mt * 128 + r) * H_ + c * KC) * 2 + p * 16;
        cp16(dst, (m ? el : eh) + goff);
    }
    // B: 256 rows x 64B, hi+lo = 2048 cp16
#pragma unroll
    for (int i = 0; i < 8; i++) {
        int id = i * 256 + tid;
        int r = id >> 3, sub = id & 7;
        int m = sub >> 2, p = sub & 3;
        uint32_t dst = tb + OFF_BH + m * B_MAT + (uint32_t)r * (LDT * 2) + p * 16;
        size_t goff = (((size_t)kt * 256 + r) * H_ + c * KC) * 2 + p * 16;
        cp16(dst, (m ? wl : wh) + goff);
    }
}

__global__ __launch_bounds__(256, 1)
void scores_wmma_kernel(const float* __restrict__ v_w) {
    extern __shared__ char smem[];
    const uint32_t sbase = smem_u32(smem);
    const int tid = threadIdx.x;
    const int wid = tid >> 5;
    const int kt = blockIdx.x;        // 0..1   (k half of 256)
    const int mt = blockIdx.y;        // 0..1023 (s tile of 128 over B*S)
    const int b  = mt >> 4;
    const int wm = wid & 1;           // warp M index (2)
    const int wn = wid >> 1;          // warp N index (4)

    float* c_s = (float*)(smem + CV_OFF);
    float* v_s = (float*)(smem + CV_OFF + 1024);
    c_s[tid] = g_c[b * H_ + kt * 256 + tid];
    v_s[tid] = v_w[kt * 256 + tid];

    wmma::fragment<wmma::accumulator, 16, 16, 16, float> acc[4][4];
#pragma unroll
    for (int i = 0; i < 4; i++)
#pragma unroll
        for (int j = 0; j < 4; j++) wmma::fill_fragment(acc[i][j], 0.f);

    fill_chunk(sbase, 0, 0, mt, kt, tid); CP_COMMIT();
    fill_chunk(sbase, 1, 1, mt, kt, tid); CP_COMMIT();

    int buf = 0;
    for (int c = 0; c < 16; c++) {
        if (c < 14) asm volatile("cp.async.wait_group 1;" ::: "memory");
        else        asm volatile("cp.async.wait_group 0;" ::: "memory");
        __syncthreads();   // all warps done with buffer (c-1)%3 -> safe to refill
        if (c + 2 < 16) {
            int nbuf = buf + 2; if (nbuf >= 3) nbuf -= 3;
            fill_chunk(sbase, nbuf, c + 2, mt, kt, tid);
            CP_COMMIT();
        }

        const char* st = smem + buf * STAGE_B;
        const __nv_bfloat16* Ah = (const __nv_bfloat16*)(st);
        const __nv_bfloat16* Al = (const __nv_bfloat16*)(st + OFF_AL);
        const __nv_bfloat16* Bh = (const __nv_bfloat16*)(st + OFF_BH);
        const __nv_bfloat16* Bl = (const __nv_bfloat16*)(st + OFF_BL);

#pragma unroll
        for (int kk = 0; kk < KC; kk += 16) {
            wmma::fragment<wmma::matrix_a, 16, 16, 16, __nv_bfloat16, wmma::row_major> ah[4], al[4];
#pragma unroll
            for (int i = 0; i < 4; i++) {
                const int row = wm * 64 + i * 16;
                wmma::load_matrix_sync(ah[i], Ah + row * LDT + kk, LDT);
                wmma::load_matrix_sync(al[i], Al + row * LDT + kk, LDT);
            }
#pragma unroll
            for (int j = 0; j < 4; j++) {
                wmma::fragment<wmma::matrix_b, 16, 16, 16, __nv_bfloat16, wmma::col_major> bh, bl;
                const int col = wn * 64 + j * 16;
                wmma::load_matrix_sync(bh, Bh + col * LDT + kk, LDT);
                wmma::load_matrix_sync(bl, Bl + col * LDT + kk, LDT);
#pragma unroll
                for (int i = 0; i < 4; i++) {
                    wmma::mma_sync(acc[i][j], ah[i], bh, acc[i][j]);
                    wmma::mma_sync(acc[i][j], ah[i], bl, acc[i][j]);
                    wmma::mma_sync(acc[i][j], al[i], bh, acc[i][j]);
                }
            }
        }
        buf++; if (buf >= 3) buf = 0;
    }

    // ---- epilogue: e[s][k] -> smem, then sum_k tanh(e + c) * v per row -----
    float* e_s = (float*)smem;         // 128 x 256 f32 = 128KB (tiles dead now)
    __syncthreads();
#pragma unroll
    for (int i = 0; i < 4; i++)
#pragma unroll
        for (int j = 0; j < 4; j++)
            wmma::store_matrix_sync(e_s + (wm * 64 + i * 16) * 256 + wn * 64 + j * 16,
                                    acc[i][j], 256, wmma::mem_row_major);
    __syncthreads();

    const int r  = tid >> 1;           // row 0..127
    const int h2 = tid & 1;            // column half
    float s = 0.f;
#pragma unroll 8
    for (int j = 0; j < 128; j++) {
        const int k = h2 * 128 + ((j + 2 * r) & 127);   // rotate: kill bank conflicts
        s += fast_tanh(e_s[r * 256 + k] + c_s[k]) * v_s[k];
    }
    s += __shfl_xor_sync(0xffffffffu, s, 1);
    if (h2 == 0)
        g_scores_part[(size_t)kt * (B_ * S_) + mt * 128 + r] = s;
}

// ---------------- K3: softmax over S per batch ------------------------------
__global__ void softmax_kernel() {
    const int b = blockIdx.x;
    const int tid = threadIdx.x;   // 256
    __shared__ float sbuf[256];

    float m = -1e30f;
    for (int i = tid; i < S_; i += 256) {
        float v = g_scores_part[0 * B_ * S_ + b * S_ + i]
                + g_scores_part[1 * B_ * S_ + b * S_ + i];
        g_weights[b * S_ + i] = v;
        m = fmaxf(m, v);
    }
    sbuf[tid] = m; __syncthreads();
    for (int o = 128; o > 0; o >>= 1) {
        if (tid < o) sbuf[tid] = fmaxf(sbuf[tid], sbuf[tid + o]);
        __syncthreads();
    }
    m = sbuf[0]; __syncthreads();

    float sum = 0.f;
    for (int i = tid; i < S_; i += 256) {
        float e = __expf(g_weights[b * S_ + i] - m);
        g_weights[b * S_ + i] = e;
        sum += e;
    }
    sbuf[tid] = sum; __syncthreads();
    for (int o = 128; o > 0; o >>= 1) {
        if (tid < o) sbuf[tid] += sbuf[tid + o];
        __syncthreads();
    }
    float inv = __fdividef(1.f, sbuf[0]);
    for (int i = tid; i < S_; i += 256) g_weights[b * S_ + i] *= inv;
}

// ---------------- K4: partial context per 128-s chunk -----------------------
__global__ void context_kernel(const float* __restrict__ enc) {
    const int sc = blockIdx.x;   // 0..15
    const int b  = blockIdx.y;
    const int tid = threadIdx.x; // 512
    __shared__ float ws[128];
    if (tid < 128) ws[tid] = g_weights[b * S_ + sc * 128 + tid];
    __syncthreads();
    const float* e = enc + ((size_t)b * S_ + sc * 128) * H_ + tid;
    float acc = 0.f;
#pragma unroll 8
    for (int s = 0; s < 128; s++) acc = fmaf(ws[s], e[(size_t)s * H_], acc);
    g_ctx_part[((size_t)sc * B_ + b) * H_ + tid] = acc;
}

// ---------------- K5: reduce partial contexts -------------------------------
__global__ void reduce_ctx(float* __restrict__ out) {
    int i = blockIdx.x * 256 + threadIdx.x;
    float s = 0.f;
#pragma unroll
    for (int ch = 0; ch < 16; ch++) s += g_ctx_part[(size_t)ch * B_ * H_ + i];
    out[i] = s;
}

extern "C" void kernel_launch(void* const* d_in, const int* in_sizes, int n_in,
                              void* d_out, int out_size) {
    const float* enc    = (const float*)d_in[0];
    const float* fin    = (const float*)d_in[1];
    const float* attn_w = (const float*)d_in[2];
    const float* attn_b = (const float*)d_in[3];
    const float* v_w    = (const float*)d_in[4];
    float* out = (float*)d_out;

    cudaFuncSetAttribute(scores_wmma_kernel,
                         cudaFuncAttributeMaxDynamicSharedMemorySize, SMEM_NEED);

    convert_enc_kernel<<<65536, 256>>>(enc);
    convert_w_kernel<<<(H_ * H_) / 256, 256>>>(attn_w);
    cfin_kernel<<<B_, H_>>>(fin, attn_w, attn_b);
    scores_wmma_kernel<<<dim3(2, 1024), 256, SMEM_NEED>>>(v_w);
    softmax_kernel<<<B_, 256>>>();
    context_kernel<<<dim3(16, B_), 512>>>(enc);
    reduce_ctx<<<(B_ * H_) / 256, 256>>>(out);
}

// round 7
// speedup vs baseline: 1.9205x; 1.1553x over previous
#include <cuda_runtime.h>
#include <cuda_bf16.h>
#include <cstdint>

#define B_ 64
#define S_ 2048
#define H_ 512

// ---------------- scratch (device globals; no allocation allowed) ----------
__device__ float g_c[B_ * H_];                       // e_fin[b,k] + attn_b[k]
__device__ float g_scores_part[4 * B_ * S_];         // per-k-tile partial scores
__device__ float g_weights[B_ * S_];                 // softmax weights
__device__ float g_ctx_part[16 * B_ * H_];           // per-s-chunk partial context
__device__ __nv_bfloat16 g_enc_hi[(size_t)B_ * S_ * H_];   // 128 MB
__device__ __nv_bfloat16 g_enc_lo[(size_t)B_ * S_ * H_];   // 128 MB
__device__ __nv_bfloat16 g_w_hi[H_ * H_];
__device__ __nv_bfloat16 g_w_lo[H_ * H_];

// ---------------- helpers ---------------------------------------------------
__device__ __forceinline__ uint32_t smem_u32(const void* p) {
    uint32_t a;
    asm("{ .reg .u64 t; cvta.to.shared.u64 t, %1; cvt.u32.u64 %0, t; }" : "=r"(a) : "l"(p));
    return a;
}
__device__ __forceinline__ void cp16(uint32_t dst, const void* src) {
    asm volatile("cp.async.cg.shared.global [%0], [%1], 16;" :: "r"(dst), "l"(src) : "memory");
}
#define CP_COMMIT() asm volatile("cp.async.commit_group;" ::: "memory")

__device__ __forceinline__ void ldsm4(uint32_t* r, uint32_t addr) {
    asm volatile("ldmatrix.sync.aligned.m8n8.x4.shared.b16 {%0,%1,%2,%3}, [%4];"
                 : "=r"(r[0]), "=r"(r[1]), "=r"(r[2]), "=r"(r[3]) : "r"(addr));
}
__device__ __forceinline__ void mma16816(float* d, const uint32_t* a,
                                         uint32_t b0, uint32_t b1) {
    asm volatile(
        "mma.sync.aligned.m16n8k16.row.col.f32.bf16.bf16.f32 "
        "{%0,%1,%2,%3}, {%4,%5,%6,%7}, {%8,%9}, {%0,%1,%2,%3};"
        : "+f"(d[0]), "+f"(d[1]), "+f"(d[2]), "+f"(d[3])
        : "r"(a[0]), "r"(a[1]), "r"(a[2]), "r"(a[3]), "r"(b0), "r"(b1));
}

__device__ __forceinline__ float fast_tanh(float x) {
    x = fminf(fmaxf(x, -15.f), 15.f);
    float e = __expf(2.f * x);
    return __fdividef(e - 1.f, e + 1.f);
}

// ---------------- K0a: enc f32 -> bf16 hi/lo split --------------------------
__global__ void convert_enc_kernel(const float* __restrict__ enc) {
    size_t i = (size_t)blockIdx.x * 256 + threadIdx.x;
    float4 x = ((const float4*)enc)[i];
    float v[4] = {x.x, x.y, x.z, x.w};
    ushort4 ho, lo;
    unsigned short* hp = &ho.x;
    unsigned short* lp = &lo.x;
#pragma unroll
    for (int j = 0; j < 4; j++) {
        __nv_bfloat16 h = __float2bfloat16(v[j]);
        __nv_bfloat16 l = __float2bfloat16(v[j] - __bfloat162float(h));
        hp[j] = __bfloat16_as_ushort(h);
        lp[j] = __bfloat16_as_ushort(l);
    }
    ((ushort4*)g_enc_hi)[i] = ho;
    ((ushort4*)g_enc_lo)[i] = lo;
}

// ---------------- K0b: w_enc f32 -> bf16 hi/lo ------------------------------
__global__ void convert_w_kernel(const float* __restrict__ attn_w) {
    int idx = blockIdx.x * 256 + threadIdx.x;
    int k = idx >> 9, h = idx & 511;
    float x = attn_w[(size_t)k * (2 * H_) + h];          // w_enc = attn_w[:, :H]
    __nv_bfloat16 hi = __float2bfloat16(x);
    g_w_hi[idx] = hi;
    g_w_lo[idx] = __float2bfloat16(x - __bfloat162float(hi));
}

// ---------------- K1: c[b,k] = fin[b]·attn_w[k, H:] + b[k] ------------------
__global__ void cfin_kernel(const float* __restrict__ fin,
                            const float* __restrict__ attn_w,
                            const float* __restrict__ attn_b) {
    __shared__ float fs[H_];
    const int b = blockIdx.x;
    const int k = threadIdx.x;
    fs[k] = fin[b * H_ + k];
    __syncthreads();
    const float* w = attn_w + (size_t)k * (2 * H_) + H_;
    float s = attn_b[k];
#pragma unroll 8
    for (int h = 0; h < H_; h++) s = fmaf(fs[h], w[h], s);
    g_c[b * H_ + k] = s;
}

// ---------------- K2: PTX mma bf16x3 GEMM + tanh/v epilogue -----------------
// CTA 128(s) x 128(k); 16 warps as 4(M) x 4(N); warp tile 32x32.
// K=512 in 8 chunks of KC=64; 3-stage cp.async pipeline; XOR-swizzled smem.
static constexpr int KC = 64;                        // 64 bf16 = 128B rows
static constexpr int MAT_B = 128 * 128;              // 16384 B per matrix tile
static constexpr int STAGE_B = 4 * MAT_B;            // 65536 (Ah, Al, Bh, Bl)
static constexpr int NSTAGE = 3;
static constexpr int CV_OFF = NSTAGE * STAGE_B;      // 196608
static constexpr int SMEM_NEED = CV_OFF + 1024;      // + c[128], v[128]
static constexpr int ELD = 132;                      // e-tile stride (f32)

// physical byte offset of logical (row r, 16B-chunk c) inside a 128x128B tile
__device__ __forceinline__ uint32_t sw(int r, int c) {
    return (uint32_t)(r * 128 + (((c) ^ (r & 7)) << 4));
}

__device__ __forceinline__ void fill_chunk(uint32_t sbase, int stage, int ck,
                                           int mt, int kt, int tid) {
    const uint32_t tb = sbase + stage * STAGE_B;
    const char* srcs[4] = {
        (const char*)g_enc_hi + ((size_t)mt * 128) * 1024,
        (const char*)g_enc_lo + ((size_t)mt * 128) * 1024,
        (const char*)g_w_hi   + ((size_t)kt * 128) * 1024,
        (const char*)g_w_lo   + ((size_t)kt * 128) * 1024 };
#pragma unroll
    for (int i = 0; i < 8; i++) {
        int id = i * 512 + tid;          // 0..4095
        int mat = id >> 10;
        int rem = id & 1023;
        int r = rem >> 3, c = rem & 7;
        cp16(tb + mat * MAT_B + sw(r, c),
             srcs[mat] + (size_t)r * 1024 + ck * 128 + c * 16);
    }
}

__global__ __launch_bounds__(512, 1)
void scores_mma_kernel(const float* __restrict__ v_w) {
    extern __shared__ char smem[];
    const uint32_t sbase = smem_u32(smem);
    const int tid = threadIdx.x;
    const int wid = tid >> 5, lane = tid & 31;
    const int kt = blockIdx.x;        // 0..3   (k tile of 128)
    const int mt = blockIdx.y;        // 0..1023 (s tile of 128 over B*S)
    const int b  = mt >> 4;
    const int wm = wid & 3;           // warp M index (4)
    const int wn = wid >> 2;          // warp N index (4)

    float* c_s = (float*)(smem + CV_OFF);
    float* v_s = (float*)(smem + CV_OFF + 512);
    if (tid < 128) {
        c_s[tid] = g_c[b * H_ + kt * 128 + tid];
        v_s[tid] = v_w[kt * 128 + tid];
    }

    float acc[2][4][4];
#pragma unroll
    for (int i = 0; i < 2; i++)
#pragma unroll
        for (int j = 0; j < 4; j++)
#pragma unroll
            for (int t = 0; t < 4; t++) acc[i][j][t] = 0.f;

    fill_chunk(sbase, 0, 0, mt, kt, tid); CP_COMMIT();
    fill_chunk(sbase, 1, 1, mt, kt, tid); CP_COMMIT();

    // per-lane ldmatrix row/chunk components (row part is swizzle-relevant)
    const int lrow_a = wm * 32 + (lane & 15);   // + i*16
    const int lrow_b = wn * 32 + (lane & 15);   // + j*16
    const int lchi = lane >> 4;                 // 16B chunk half, + kk*2

    int buf = 0;
    for (int ck = 0; ck < 8; ck++) {
        if (ck < 6) asm volatile("cp.async.wait_group 1;" ::: "memory");
        else        asm volatile("cp.async.wait_group 0;" ::: "memory");
        __syncthreads();
        if (ck + 2 < 8) {
            int nbuf = buf + 2; if (nbuf >= 3) nbuf -= 3;
            fill_chunk(sbase, nbuf, ck + 2, mt, kt, tid);
            CP_COMMIT();
        }

        const uint32_t stb = sbase + buf * STAGE_B;
#pragma unroll
        for (int kk = 0; kk < 4; kk++) {
            const int c16 = kk * 2 + lchi;
            uint32_t ah[2][4], al[2][4], bh[2][4], bl[2][4];
#pragma unroll
            for (int i = 0; i < 2; i++) {
                ldsm4(ah[i], stb + 0 * MAT_B + sw(lrow_a + i * 16, c16));
                ldsm4(al[i], stb + 1 * MAT_B + sw(lrow_a + i * 16, c16));
            }
#pragma unroll
            for (int j = 0; j < 2; j++) {
                ldsm4(bh[j], stb + 2 * MAT_B + sw(lrow_b + j * 16, c16));
                ldsm4(bl[j], stb + 3 * MAT_B + sw(lrow_b + j * 16, c16));
            }
            // chain hh: 8 MMAs, then hl, then lh  (same-acc spacing = 8)
#pragma unroll
            for (int i = 0; i < 2; i++)
#pragma unroll
                for (int j = 0; j < 2; j++) {
                    mma16816(acc[i][j * 2 + 0], ah[i], bh[j][0], bh[j][2]);
                    mma16816(acc[i][j * 2 + 1], ah[i], bh[j][1], bh[j][3]);
                }
#pragma unroll
            for (int i = 0; i < 2; i++)
#pragma unroll
                for (int j = 0; j < 2; j++) {
                    mma16816(acc[i][j * 2 + 0], ah[i], bl[j][0], bl[j][2]);
                    mma16816(acc[i][j * 2 + 1], ah[i], bl[j][1], bl[j][3]);
                }
#pragma unroll
            for (int i = 0; i < 2; i++)
#pragma unroll
                for (int j = 0; j < 2; j++) {
                    mma16816(acc[i][j * 2 + 0], al[i], bh[j][0], bh[j][2]);
                    mma16816(acc[i][j * 2 + 1], al[i], bh[j][1], bh[j][3]);
                }
        }
        buf++; if (buf >= 3) buf = 0;
    }

    // ---- epilogue: acc -> e_s (stride 132), then row-sum tanh(e+c)*v -------
    float* e_s = (float*)smem;          // 128 x 132 f32 = 67.6KB (stages dead)
    __syncthreads();
#pragma unroll
    for (int i = 0; i < 2; i++)
#pragma unroll
        for (int j = 0; j < 4; j++) {
            const int row = wm * 32 + i * 16 + (lane >> 2);
            const int col = wn * 32 + j * 8 + (lane & 3) * 2;
            *(float2*)&e_s[row * ELD + col]       = make_float2(acc[i][j][0], acc[i][j][1]);
            *(float2*)&e_s[(row + 8) * ELD + col] = make_float2(acc[i][j][2], acc[i][j][3]);
        }
    __syncthreads();

    const int r = tid >> 2;            // row 0..127
    const int q = tid & 3;             // column quarter
    float s = 0.f;
#pragma unroll 8
    for (int j = 0; j < 32; j++) {
        const int k = q * 32 + ((j + r + q * 8) & 31);
        s += fast_tanh(e_s[r * ELD + k] + c_s[k]) * v_s[k];
    }
    s += __shfl_xor_sync(0xffffffffu, s, 1);
    s += __shfl_xor_sync(0xffffffffu, s, 2);
    if (q == 0)
        g_scores_part[(size_t)kt * (B_ * S_) + mt * 128 + r] = s;
}

// ---------------- K3: softmax over S per batch ------------------------------
__global__ void softmax_kernel() {
    const int b = blockIdx.x;
    const int tid = threadIdx.x;   // 256
    __shared__ float sbuf[256];

    float m = -1e30f;
    for (int i = tid; i < S_; i += 256) {
        float v = g_scores_part[0 * B_ * S_ + b * S_ + i]
                + g_scores_part[1 * B_ * S_ + b * S_ + i]
                + g_scores_part[2 * B_ * S_ + b * S_ + i]
                + g_scores_part[3 * B_ * S_ + b * S_ + i];
        g_weights[b * S_ + i] = v;
        m = fmaxf(m, v);
    }
    sbuf[tid] = m; __syncthreads();
    for (int o = 128; o > 0; o >>= 1) {
        if (tid < o) sbuf[tid] = fmaxf(sbuf[tid], sbuf[tid + o]);
        __syncthreads();
    }
    m = sbuf[0]; __syncthreads();

    float sum = 0.f;
    for (int i = tid; i < S_; i += 256) {
        float e = __expf(g_weights[b * S_ + i] - m);
        g_weights[b * S_ + i] = e;
        sum += e;
    }
    sbuf[tid] = sum; __syncthreads();
    for (int o = 128; o > 0; o >>= 1) {
        if (tid < o) sbuf[tid] += sbuf[tid + o];
        __syncthreads();
    }
    float inv = __fdividef(1.f, sbuf[0]);
    for (int i = tid; i < S_; i += 256) g_weights[b * S_ + i] *= inv;
}

// ---------------- K4: partial context per 128-s chunk -----------------------
__global__ void context_kernel(const float* __restrict__ enc) {
    const int sc = blockIdx.x;   // 0..15
    const int b  = blockIdx.y;
    const int tid = threadIdx.x; // 512
    __shared__ float ws[128];
    if (tid < 128) ws[tid] = g_weights[b * S_ + sc * 128 + tid];
    __syncthreads();
    const float* e = enc + ((size_t)b * S_ + sc * 128) * H_ + tid;
    float acc = 0.f;
#pragma unroll 8
    for (int s = 0; s < 128; s++) acc = fmaf(ws[s], e[(size_t)s * H_], acc);
    g_ctx_part[((size_t)sc * B_ + b) * H_ + tid] = acc;
}

// ---------------- K5: reduce partial contexts -------------------------------
__global__ void reduce_ctx(float* __restrict__ out) {
    int i = blockIdx.x * 256 + threadIdx.x;
    float s = 0.f;
#pragma unroll
    for (int ch = 0; ch < 16; ch++) s += g_ctx_part[(size_t)ch * B_ * H_ + i];
    out[i] = s;
}

extern "C" void kernel_launch(void* const* d_in, const int* in_sizes, int n_in,
                              void* d_out, int out_size) {
    const float* enc    = (const float*)d_in[0];
    const float* fin    = (const float*)d_in[1];
    const float* attn_w = (const float*)d_in[2];
    const float* attn_b = (const float*)d_in[3];
    const float* v_w    = (const float*)d_in[4];
    float* out = (float*)d_out;

    cudaFuncSetAttribute(scores_mma_kernel,
                         cudaFuncAttributeMaxDynamicSharedMemorySize, SMEM_NEED);

    convert_enc_kernel<<<65536, 256>>>(enc);
    convert_w_kernel<<<(H_ * H_) / 256, 256>>>(attn_w);
    cfin_kernel<<<B_, H_>>>(fin, attn_w, attn_b);
    scores_mma_kernel<<<dim3(4, 1024), 512, SMEM_NEED>>>(v_w);
    softmax_kernel<<<B_, 256>>>();
    context_kernel<<<dim3(16, B_), 512>>>(enc);
    reduce_ctx<<<(B_ * H_) / 256, 256>>>(out);
}